// round 12
// baseline (speedup 1.0000x reference)
#include <cuda_runtime.h>
#include <math.h>

#define Bsz 64
#define Ssz 512
#define Hsz 400
#define Vsz 32000
#define Lsz 16
#define HC   4             // score h-chunks (100 h each)
#define HCW  100
#define RBLKS 128          // recurrence blocks: 8 bgroups x 16 jtiles
#define SBLKS 256          // score blocks: 64 b x 4 hc
#define NBLK 384
#define NTHR 256
#define HP   408           // hS row pitch (floats)

// ---------------- device globals ----------------
__device__ float g_hA[Bsz * Hsz];
__device__ float g_hB[Bsz * Hsz];
__device__ float g_x[Bsz * Hsz];
__device__ float g_xB[Lsz * Bsz * Hsz];
__device__ float g_giB[Lsz][Bsz][1200];
__device__ float g_encT[Bsz][Hsz][Ssz];
__device__ float g_scpart[2][HC][Bsz][Ssz];
__device__ int   g_cnt[2][Bsz];
__device__ int   g_subH[Lsz][16 * 64];      // 128 arrivers: 16 subs of 8
__device__ int   g_subF[Lsz][16 * 64];      // 256 arrivers: 16 subs of 16
__device__ int   g_subBar[2][24 * 64];      // 384 arrivers: 24 subs of 16
__device__ int   g_hCnt[Lsz],     g_hDone[Lsz];
__device__ int   g_fusedCnt[Lsz], g_fusedDone[Lsz];
__device__ int   g_batchCnt[Lsz], g_batchDone[Lsz];
__device__ int   g_bar[2], g_barDone[2];

// ---------------- f32x2 helpers ----------------
__device__ __forceinline__ unsigned long long pk2(float x, float y) {
    unsigned long long r;
    asm("mov.b64 %0, {%1, %2};" : "=l"(r) : "f"(x), "f"(y));
    return r;
}
__device__ __forceinline__ void ffma2(unsigned long long& d,
                                      unsigned long long a, unsigned long long b) {
    asm("fma.rn.f32x2 %0, %1, %2, %0;" : "+l"(d) : "l"(a), "l"(b));
}
__device__ __forceinline__ float2 up2(unsigned long long v) {
    float2 f;
    asm("mov.b64 {%0, %1}, %2;" : "=f"(f.x), "=f"(f.y) : "l"(v));
    return f;
}

// ---------------- sync primitives ----------------
__device__ __forceinline__ void wait_flag(int* flag) {
    if (threadIdx.x == 0) {
        int v;
        while (true) {
            asm volatile("ld.acquire.gpu.b32 %0, [%1];" : "=r"(v) : "l"(flag) : "memory");
            if (v) break;
            __nanosleep(32);
        }
    }
    __syncthreads();
}
__device__ __forceinline__ void arrive_h(int* subs, int subIdx, int subTarget,
                                         int* root, int rootTarget, int* flag) {
    __threadfence();
    __syncthreads();
    if (threadIdx.x == 0) {
        int old = atomicAdd(&subs[subIdx * 64], 1);
        if (old == subTarget - 1) {
            int r = atomicAdd(root, 1);
            if (r == rootTarget - 1)
                asm volatile("st.release.gpu.b32 [%0], %1;" :: "l"(flag), "r"(1) : "memory");
        }
    }
}
__device__ __forceinline__ void arrive_flat(int* cnt, int target, int* flag) {
    __threadfence();
    __syncthreads();
    if (threadIdx.x == 0) {
        int old = atomicAdd(cnt, 1);
        if (old == target - 1)
            asm volatile("st.release.gpu.b32 [%0], %1;" :: "l"(flag), "r"(1) : "memory");
    }
}

// ---------------- reset ----------------
__global__ __launch_bounds__(256) void reset_kernel() {
    int i = threadIdx.x;
    if (i < Lsz) {
        g_hCnt[i] = 0;     g_hDone[i] = 0;
        g_fusedCnt[i] = 0; g_fusedDone[i] = 0;
        g_batchCnt[i] = 0; g_batchDone[i] = 0;
    }
    if (i < 2) { g_bar[i] = 0; g_barDone[i] = 0; }
    if (i < Bsz) { g_cnt[0][i] = 0; g_cnt[1][i] = 0; }
    for (int k = i; k < Lsz * 16; k += 256) {
        g_subH[k >> 4][(k & 15) * 64] = 0;
        g_subF[k >> 4][(k & 15) * 64] = 0;
    }
    for (int k = i; k < 2 * 24; k += 256) g_subBar[k / 24][(k % 24) * 64] = 0;
}

// ---------------- persistent kernel ----------------
__global__ __launch_bounds__(NTHR, 4) void persist_kernel(
    const float* __restrict__ eh,
    const float* __restrict__ enc,
    const int* __restrict__ lens,
    const int* __restrict__ uttrs,
    const int* __restrict__ targets,
    const int* __restrict__ slot_p,
    const int* __restrict__ use_tf_p,
    const float* __restrict__ emb,
    const float* __restrict__ slot_emb,
    const float* __restrict__ Wih,
    const float* __restrict__ Whh,
    const float* __restrict__ bih,
    const float* __restrict__ bhh,
    float* __restrict__ out,
    int out_size, int write_preds)
{
    __shared__ float pool[6700];   // 26.8 KB

    int bx = blockIdx.x;
    int tid = threadIdx.x;
    int gidx = bx * NTHR + tid;
    const int nt = NBLK * NTHR;

    // ============ Phase 0: zero t=0 rows + pad, init h/x, xbuild ============
    {
        for (int i = gidx; i < Bsz * (Vsz / 4); i += nt) {
            int b = i / (Vsz / 4), q = i % (Vsz / 4);
            float4* p = (float4*)(out + (size_t)b * Lsz * Vsz) + q;
            asm volatile("st.global.cs.v4.f32 [%0], {%1, %2, %3, %4};"
                         :: "l"(p), "f"(0.f), "f"(0.f), "f"(0.f), "f"(0.f) : "memory");
        }
        for (int i = (Bsz * Lsz * Vsz) + gidx; i < out_size; i += nt)
            asm volatile("st.global.cs.f32 [%0], %1;" :: "l"(out + i), "f"(0.f) : "memory");

        int slot = slot_p[0];
        for (int i = gidx; i < Bsz * Hsz; i += nt) {
            g_hA[i] = eh[i];
            g_x[i] = slot_emb[slot * Hsz + i % Hsz];
        }
        for (int i = gidx; i < Lsz * Bsz * 100; i += nt) {
            int row = i / 100, q = i % 100;
            int t = row >> 6, b = row & 63;
            const float* src = (t == 0) ? (slot_emb + slot * Hsz)
                                        : (emb + (size_t)targets[b * Lsz + (t - 1)] * Hsz);
            ((float4*)(g_xB + (size_t)row * Hsz))[q] = ((const float4*)src)[q];
        }
    }
    arrive_h(g_subBar[0], bx % 24, 16, &g_bar[0], 24, &g_barDone[0]);
    wait_flag(&g_barDone[0]);

    int tf = use_tf_p[0];

    // ============ Phase 1: RB -> transpose; score blocks -> batch gi ============
    if (bx < RBLKS) {
        // transpose enc[b][s][h] -> encT[b][h][s]
        float (*tile)[33] = (float(*)[33])pool;
        int tx = tid & 31, ty = tid >> 5;    // 32 x 8
        for (int tt = bx; tt < Bsz * 16 * 13; tt += RBLKS) {
            int b = tt / (16 * 13);
            int rem = tt % (16 * 13);
            int s0 = (rem / 13) * 32;
            int h0 = (rem % 13) * 32;
            __syncthreads();
            #pragma unroll
            for (int i = 0; i < 32; i += 8) {
                int s = s0 + ty + i, h = h0 + tx;
                if (h < Hsz) tile[ty + i][tx] = enc[((size_t)b * Ssz + s) * Hsz + h];
            }
            __syncthreads();
            #pragma unroll
            for (int i = 0; i < 32; i += 8) {
                int h = h0 + ty + i, s = s0 + tx;
                if (h < Hsz) g_encT[b][h][s] = tile[tx][ty + i];
            }
        }
    } else if (tf) {
        // batch gi: score block fb does units fb and fb+256 (u<480)
        int fb = bx - RBLKS;
        float (*As)[68] = (float(*)[68])pool;              // 50 x 68
        float (*Ws)[44] = (float(*)[44])(pool + 3400);     // 50 x 44
        for (int u = fb; u < 480; u += SBLKS) {
            int bt = u / 30;
            int jbase = (u % 30) * 40;
            const float* A = g_xB + (size_t)bt * Bsz * Hsz;
            int tj = tid / 16;     // 0..15 (active < 10)
            int tb2 = tid % 16;
            int b0 = 4 * tb2, j0 = 4 * tj;
            bool active = (tj < 10);
            unsigned long long acc[4][2];
            #pragma unroll
            for (int a = 0; a < 4; a++) { acc[a][0] = 0ULL; acc[a][1] = 0ULL; }

            for (int kt = 0; kt < 8; kt++) {
                int kbase = kt * 50;
                __syncthreads();
                for (int i = tid; i < 1600; i += NTHR) {
                    int q = i >> 6, b = i & 63;
                    float2 v = *(const float2*)&A[b * Hsz + kbase + 2 * q];
                    As[2 * q + 0][b] = v.x;
                    As[2 * q + 1][b] = v.y;
                }
                for (int i = tid; i < 1000; i += NTHR) {
                    int q = i / 40, j = i % 40;
                    float2 v = *(const float2*)&Wih[(size_t)(jbase + j) * Hsz + kbase + 2 * q];
                    Ws[2 * q + 0][j] = v.x;
                    Ws[2 * q + 1][j] = v.y;
                }
                __syncthreads();
                if (active) {
                    #pragma unroll 5
                    for (int k = 0; k < 50; k++) {
                        float4 av = *(const float4*)&As[k][b0];
                        float4 wv = *(const float4*)&Ws[k][j0];
                        unsigned long long a01 = pk2(av.x, av.y);
                        unsigned long long a23 = pk2(av.z, av.w);
                        ffma2(acc[0][0], a01, pk2(wv.x, wv.x)); ffma2(acc[0][1], a23, pk2(wv.x, wv.x));
                        ffma2(acc[1][0], a01, pk2(wv.y, wv.y)); ffma2(acc[1][1], a23, pk2(wv.y, wv.y));
                        ffma2(acc[2][0], a01, pk2(wv.z, wv.z)); ffma2(acc[2][1], a23, pk2(wv.z, wv.z));
                        ffma2(acc[3][0], a01, pk2(wv.w, wv.w)); ffma2(acc[3][1], a23, pk2(wv.w, wv.w));
                    }
                }
            }
            if (active) {
                #pragma unroll
                for (int p = 0; p < 2; p++) {
                    float2 f0 = up2(acc[0][p]);
                    float2 f1 = up2(acc[1][p]);
                    float2 f2 = up2(acc[2][p]);
                    float2 f3 = up2(acc[3][p]);
                    *(float4*)&g_giB[bt][b0 + 2 * p][jbase + j0]     = make_float4(f0.x, f1.x, f2.x, f3.x);
                    *(float4*)&g_giB[bt][b0 + 2 * p + 1][jbase + j0] = make_float4(f0.y, f1.y, f2.y, f3.y);
                }
            }
            arrive_flat(&g_batchCnt[bt], 30, &g_batchDone[bt]);
            __syncthreads();
        }
    }
    arrive_h(g_subBar[1], bx % 24, 16, &g_bar[1], 24, &g_barDone[1]);
    wait_flag(&g_barDone[1]);

    // ============ Phase 2: recurrence ============
    if (bx < RBLKS) {
        // -------- recurrence block: full-K gh + gates, no partials --------
        float* hS = pool;            // [8][HP]
        float* xS = pool + 8 * HP;   // [8][HP]  (!tf only)
        int bg = bx >> 4;            // 0..7
        int jt = bx & 15;            // 0..15
        int jl = tid >> 3;           // 0..31 (active < 25)
        int tb = tid & 7;            // 0..7
        bool active = (jl < 25);
        int j = jt * 25 + jl;        // 0..399
        int b = bg * 8 + tb;

        float bi_r = 0.f, bi_z = 0.f, bi_n = 0.f, bh_r = 0.f, bh_z = 0.f, bh_n = 0.f;
        if (active) {
            bi_r = bih[j]; bi_z = bih[400 + j]; bi_n = bih[800 + j];
            bh_r = bhh[j]; bh_z = bhh[400 + j]; bh_n = bhh[800 + j];
        }
        const float* wr = Whh + (size_t)j * Hsz;
        const float* wz = Whh + (size_t)(400 + j) * Hsz;
        const float* wn = Whh + (size_t)(800 + j) * Hsz;
        const float* ir_ = Wih + (size_t)j * Hsz;
        const float* iz_ = Wih + (size_t)(400 + j) * Hsz;
        const float* in_ = Wih + (size_t)(800 + j) * Hsz;

        for (int t = 0; t < Lsz; t++) {
            if (t > 0) wait_flag(&g_hDone[t - 1]);
            if (t >= 2) wait_flag(&g_fusedDone[t - 2]);          // h-buffer + scpart reuse
            if (!tf && t > 0) wait_flag(&g_fusedDone[t - 1]);    // x(t) from tail(t-1)

            const float* hin  = (t & 1) ? g_hB : g_hA;
            float*       hout = (t & 1) ? g_hA : g_hB;

            // stage h_prev rows for this bgroup: 8 x 400 floats
            __syncthreads();
            for (int i = tid; i < 800; i += NTHR) {
                float4 v = *(const float4*)&hin[bg * 3200 + 4 * i];
                int flat = 4 * i, bl = flat / 400, col = flat % 400;
                *(float4*)&hS[bl * HP + col] = v;
            }
            if (!tf) {
                for (int i = tid; i < 800; i += NTHR) {
                    float4 v = *(const float4*)&g_x[bg * 3200 + 4 * i];
                    int flat = 4 * i, bl = flat / 400, col = flat % 400;
                    *(float4*)&xS[bl * HP + col] = v;
                }
            }
            __syncthreads();

            if (active) {
                const float* hb = &hS[tb * HP];
                unsigned long long aR0 = 0, aR1 = 0, aZ0 = 0, aZ1 = 0, aN0 = 0, aN1 = 0;
                #pragma unroll 4
                for (int k = 0; k < Hsz; k += 4) {
                    float4 h4 = *(const float4*)&hb[k];
                    float4 r4 = __ldg((const float4*)(wr + k));
                    float4 z4 = __ldg((const float4*)(wz + k));
                    float4 n4 = __ldg((const float4*)(wn + k));
                    unsigned long long h01 = pk2(h4.x, h4.y);
                    unsigned long long h23 = pk2(h4.z, h4.w);
                    ffma2(aR0, h01, pk2(r4.x, r4.y)); ffma2(aR1, h23, pk2(r4.z, r4.w));
                    ffma2(aZ0, h01, pk2(z4.x, z4.y)); ffma2(aZ1, h23, pk2(z4.z, z4.w));
                    ffma2(aN0, h01, pk2(n4.x, n4.y)); ffma2(aN1, h23, pk2(n4.z, n4.w));
                }
                float2 r0 = up2(aR0), r1 = up2(aR1);
                float2 z0 = up2(aZ0), z1 = up2(aZ1);
                float2 n0 = up2(aN0), n1 = up2(aN1);
                float gh_r = (r0.x + r0.y) + (r1.x + r1.y);
                float gh_z = (z0.x + z0.y) + (z1.x + z1.y);
                float gh_n = (n0.x + n0.y) + (n1.x + n1.y);

                float gi_r, gi_z, gi_n;
                if (tf) {
                    gi_r = g_giB[t][b][j];
                    gi_z = g_giB[t][b][400 + j];
                    gi_n = g_giB[t][b][800 + j];
                } else {
                    const float* xb = &xS[tb * HP];
                    unsigned long long iR0 = 0, iR1 = 0, iZ0 = 0, iZ1 = 0, iN0 = 0, iN1 = 0;
                    #pragma unroll 4
                    for (int k = 0; k < Hsz; k += 4) {
                        float4 x4 = *(const float4*)&xb[k];
                        float4 r4 = __ldg((const float4*)(ir_ + k));
                        float4 z4 = __ldg((const float4*)(iz_ + k));
                        float4 n4 = __ldg((const float4*)(in_ + k));
                        unsigned long long x01 = pk2(x4.x, x4.y);
                        unsigned long long x23 = pk2(x4.z, x4.w);
                        ffma2(iR0, x01, pk2(r4.x, r4.y)); ffma2(iR1, x23, pk2(r4.z, r4.w));
                        ffma2(iZ0, x01, pk2(z4.x, z4.y)); ffma2(iZ1, x23, pk2(z4.z, z4.w));
                        ffma2(iN0, x01, pk2(n4.x, n4.y)); ffma2(iN1, x23, pk2(n4.z, n4.w));
                    }
                    float2 a0 = up2(iR0), a1 = up2(iR1);
                    float2 b0_ = up2(iZ0), b1 = up2(iZ1);
                    float2 c0 = up2(iN0), c1 = up2(iN1);
                    gi_r = (a0.x + a0.y) + (a1.x + a1.y);
                    gi_z = (b0_.x + b0_.y) + (b1.x + b1.y);
                    gi_n = (c0.x + c0.y) + (c1.x + c1.y);
                }

                float r = 1.f / (1.f + expf(-(gi_r + bi_r + gh_r + bh_r)));
                float z = 1.f / (1.f + expf(-(gi_z + bi_z + gh_z + bh_z)));
                float n = tanhf(gi_n + bi_n + r * (gh_n + bh_n));
                float hp = hb[j];
                hout[b * Hsz + j] = (1.f - z) * n + z * hp;
            }

            arrive_h(g_subH[t], bx & 15, 8, &g_hCnt[t], 16, &g_hDone[t]);
        }
    } else {
        // -------- score role: scores + tail + lazy zero --------
        float* sh   = pool;                 // 128
        float* redv = pool + 128;           // 256
        int*   redi = (int*)(pool + 384);   // 256
        float* flg  = pool + 640;

        int fb = bx - RBLKS;
        int b  = fb >> 2;
        int hc = fb & 3;
        int len = lens[b];
        int sub = fb & 15;
        __syncthreads();

        for (int t = 0; t < Lsz; t++) {
            int par = t & 1;
            if (t >= 2) wait_flag(&g_fusedDone[t - 2]);
            wait_flag(&g_hDone[t]);

            const float* hnew = (t & 1) ? g_hA : g_hB;   // hout of step t
            if (tid < 25)
                ((float4*)sh)[tid] = ((const float4*)(hnew + b * Hsz + hc * HCW))[tid];
            __syncthreads();

            int s0 = 2 * tid;
            if (s0 < len) {
                const float* ep = &g_encT[b][hc * HCW][s0];
                float ax = 0.f, ay = 0.f;
                #pragma unroll 5
                for (int h = 0; h < HCW; h++) {
                    float hv = sh[h];
                    float2 e = *(const float2*)&ep[(size_t)h * Ssz];
                    ax += e.x * hv;
                    ay += e.y * hv;
                }
                *(float2*)&g_scpart[par][hc][b][s0] = make_float2(ax, ay);
            }

            // per-b arrival (4 arrivers, distinct lines)
            __threadfence();
            __syncthreads();
            if (tid == 0) {
                int old = atomicAdd(&g_cnt[par][b], 1);
                flg[0] = (old == HC - 1) ? 1.f : 0.f;
            }
            __syncthreads();
            bool last = (flg[0] != 0.f);

            if (last) {
                __threadfence();
                if (tid == 0) g_cnt[par][b] = 0;

                float v[2];
                #pragma unroll
                for (int q = 0; q < 2; q++) {
                    int s = tid + NTHR * q;
                    if (s < len) {
                        float sum = 0.f;
                        #pragma unroll
                        for (int p = 0; p < HC; p++) sum += g_scpart[par][p][b][s];
                        v[q] = sum;
                    } else {
                        v[q] = -INFINITY;
                    }
                }
                float mv = v[0]; int mi = tid;
                if (v[1] > mv) { mv = v[1]; mi = tid + NTHR; }
                redv[tid] = mv;
                redi[tid] = mi;
                __syncthreads();
                for (int st = 128; st > 0; st >>= 1) {
                    if (tid < st) {
                        float w2 = redv[tid + st];
                        int   i2 = redi[tid + st];
                        if (w2 > redv[tid] || (w2 == redv[tid] && i2 < redi[tid])) {
                            redv[tid] = w2;
                            redi[tid] = i2;
                        }
                    }
                    __syncthreads();
                }
                float m = redv[0];
                int amax = redi[0];
                __syncthreads();

                float e0 = expf(v[0] - m);
                float e1 = expf(v[1] - m);
                redv[tid] = e0 + e1;
                __syncthreads();
                for (int st = 128; st > 0; st >>= 1) {
                    if (tid < st) redv[tid] += redv[tid + st];
                    __syncthreads();
                }
                float inv = 1.f / redv[0];

                float* orow = out + (size_t)b * Lsz * Vsz + (size_t)t * Vsz;
                if (tid < len)
                    atomicAdd(&orow[uttrs[b * Ssz + tid]], e0 * inv);
                if (tid + NTHR < len)
                    atomicAdd(&orow[uttrs[b * Ssz + tid + NTHR]], e1 * inv);

                if (tid == 0) {
                    int pred = uttrs[b * Ssz + amax];
                    if (write_preds)
                        out[(size_t)Bsz * Lsz * Vsz + (size_t)t * Bsz + b] = (float)pred;
                    ((int*)flg)[1] = tf ? targets[b * Lsz + t] : pred;
                }
                __syncthreads();
                if (!tf) {
                    int nxt = ((int*)flg)[1];
                    if (tid < 100)
                        ((float4*)(g_x + b * Hsz))[tid] =
                            ((const float4*)(emb + (size_t)nxt * Hsz))[tid];
                }
            }

            arrive_h(g_subF[t], sub, 16, &g_fusedCnt[t], 16, &g_fusedDone[t]);

            // lazy zero of row (b, t+1) in post-arrive slack
            if (t + 1 < Lsz) {
                float* row = out + (size_t)b * Lsz * Vsz + (size_t)(t + 1) * Vsz;
                for (int i = hc * NTHR + tid; i < Vsz / 4; i += HC * NTHR) {
                    float4* p = (float4*)row + i;
                    asm volatile("st.global.cs.v4.f32 [%0], {%1, %2, %3, %4};"
                                 :: "l"(p), "f"(0.f), "f"(0.f), "f"(0.f), "f"(0.f) : "memory");
                }
            }
        }
    }
}

// ---------------- launch ----------------
extern "C" void kernel_launch(void* const* d_in, const int* in_sizes, int n_in,
                              void* d_out, int out_size) {
    const float* eh       = (const float*)d_in[0];
    const float* enc      = (const float*)d_in[1];
    const int*   lens     = (const int*)d_in[2];
    const int*   uttrs    = (const int*)d_in[3];
    const int*   targets  = (const int*)d_in[4];
    const int*   slot     = (const int*)d_in[5];
    const int*   use_tf   = (const int*)d_in[6];
    const float* emb      = (const float*)d_in[7];
    const float* slot_emb = (const float*)d_in[8];
    const float* Wih      = (const float*)d_in[9];
    const float* Whh      = (const float*)d_in[10];
    const float* bih      = (const float*)d_in[11];
    const float* bhh      = (const float*)d_in[12];
    float* out = (float*)d_out;

    int write_preds = out_size > Bsz * Lsz * Vsz;
    reset_kernel<<<1, 256>>>();
    persist_kernel<<<NBLK, NTHR>>>(eh, enc, lens, uttrs, targets, slot, use_tf,
                                   emb, slot_emb, Wih, Whh, bih, bhh,
                                   out, out_size, write_preds);
}